// round 5
// baseline (speedup 1.0000x reference)
#include <cuda_runtime.h>

#define NBLK 147
#define WPB  14       // warps per block (448 threads); 147*14=2058 >= 2048 rows
#define TT   512
#define HH   32
#define BATCH 2048

typedef unsigned long long u64;

__device__ __forceinline__ u64 pk2(float a, float b) {
    u64 r; asm("mov.b64 %0,{%1,%2};" : "=l"(r) : "f"(a), "f"(b)); return r;
}
__device__ __forceinline__ void upk2(u64 v, float& a, float& b) {
    asm("mov.b64 {%0,%1},%2;" : "=f"(a), "=f"(b) : "l"(v));
}
__device__ __forceinline__ u64 ffma2(u64 a, u64 b, u64 c) {
    u64 d; asm("fma.rn.f32x2 %0,%1,%2,%3;" : "=l"(d) : "l"(a), "l"(b), "l"(c)); return d;
}
__device__ __forceinline__ float ex2f(float x) {
    float y; asm("ex2.approx.f32 %0,%1;" : "=f"(y) : "f"(x)); return y;
}
__device__ __forceinline__ float rcpf(float x) {
    float y; asm("rcp.approx.f32 %0,%1;" : "=f"(y) : "f"(x)); return y;
}
// plain versions for the one-off backward step
__device__ __forceinline__ float sigm(float v) {
    return rcpf(1.0f + ex2f(v * -1.4426950408889634f));
}
__device__ __forceinline__ float tanhfast(float v) {
    float s = rcpf(1.0f + ex2f(v * -2.8853900817779268f));
    return fmaf(2.0f, s, -1.0f);
}
// pre-scaled: argument already multiplied by -log2e (sigm) / -2log2e (tanh)
__device__ __forceinline__ float sigm_s(float vs) {
    return rcpf(1.0f + ex2f(vs));
}
__device__ __forceinline__ float tanh_s(float vs) {
    return fmaf(2.0f, rcpf(1.0f + ex2f(vs)), -1.0f);
}

#define NL2E  (-1.4426950408889634f)   // -log2(e)
#define N2L2E (-2.8853900817779268f)   // -2*log2(e)

__global__ void __launch_bounds__(WPB * 32, 1)
gru_bidir_kernel(const float* __restrict__ x,
                 const float* __restrict__ Wihf, const float* __restrict__ Whhf,
                 const float* __restrict__ bihf, const float* __restrict__ bhhf,
                 const float* __restrict__ Wihb, const float* __restrict__ Whhb,
                 const float* __restrict__ bihb, const float* __restrict__ bhhb,
                 const float* __restrict__ W1,  const float* __restrict__ b1,
                 const float* __restrict__ W2,  const float* __restrict__ b2,
                 float* __restrict__ out)
{
    __shared__ float xs[WPB][TT];                          // 28 KB: x staged, 1 batch/warp
    __shared__ __align__(16) float hbuf[WPB][2][HH];       // ping-pong hidden (read as u64x2)
    __shared__ __align__(16) float vbuf[WPB][2 * HH];      // concat(h_f, h_b) for MLP
    __shared__ float  w1s[16 * 65];                        // padded stride 65 -> conflict-free
    __shared__ float  b1s[16], w2s[16];

    const int tid  = threadIdx.x;
    const int lane = tid & 31;
    const int warp = tid >> 5;
    const int bb   = blockIdx.x * WPB + warp;  // batch row owned by this warp
    const int j    = lane;                     // hidden dim owned by this lane
    const bool active = (bb < BATCH);

    // ---- stage MLP weights (block-wide) ----
    for (int i = tid; i < 16 * 64; i += WPB * 32) {
        int u = i >> 6, k = i & 63;
        w1s[u * 65 + k] = W1[i];
    }
    if (tid < 16) { b1s[tid] = b1[tid]; w2s[tid] = W2[tid]; }

    // ---- load recurrent weights, PRE-SCALED: r,z rows * -log2e ; n rows * -2log2e ----
    u64 wr[16], wz[16], wn[16];
    {
        const float2* pr = (const float2*)(Whhf + (j)      * HH);
        const float2* pz = (const float2*)(Whhf + (j + 32) * HH);
        const float2* pn = (const float2*)(Whhf + (j + 64) * HH);
#pragma unroll
        for (int k = 0; k < 16; k++) {
            float2 t0 = pr[k]; wr[k] = pk2(t0.x * NL2E,  t0.y * NL2E);
            float2 t1 = pz[k]; wz[k] = pk2(t1.x * NL2E,  t1.y * NL2E);
            float2 t2 = pn[k]; wn[k] = pk2(t2.x * N2L2E, t2.y * N2L2E);
        }
    }
    const float wxr = Wihf[j] * NL2E, wxz = Wihf[j + 32] * NL2E, wxn = Wihf[j + 64] * N2L2E;
    const float br   = (bihf[j]      + bhhf[j])      * NL2E;
    const float bz   = (bihf[j + 32] + bhhf[j + 32]) * NL2E;
    const float bn_i = bihf[j + 64] * N2L2E;     // input-side n bias (outside r*), scaled
    const float bn_h = bhhf[j + 64] * N2L2E;     // hidden-side n bias (inside r*), scaled

    float h = 0.f;

    if (active) {
        // ---- stage this warp's x row ----
        for (int i = lane; i < TT; i += 32)
            xs[warp][i] = x[bb * TT + i];

        hbuf[warp][0][j] = 0.f;
        __syncwarp();

        const float* xp = &xs[warp][0];
        int pp = 0;

        // ================= forward GRU scan =================
#pragma unroll 1
        for (int t = 0; t < TT; t++) {
            float xv = xp[t];
            float sr = fmaf(xv, wxr, br);     // scaled by -log2e
            float sz = fmaf(xv, wxz, bz);
            float sn = fmaf(xv, wxn, bn_i);   // scaled by -2log2e

            const ulonglong2* hb2 = (const ulonglong2*)&hbuf[warp][pp][0];

            // fold per-step scalars into accumulator inits
            u64 ar = pk2(sr, 0.f);
            u64 az = pk2(sz, 0.f);
            u64 an = pk2(bn_h, 0.f);
#pragma unroll
            for (int k2 = 0; k2 < 8; k2++) {
                ulonglong2 v = hb2[k2];
                ar = ffma2(v.x, wr[2 * k2], ar);
                az = ffma2(v.x, wz[2 * k2], az);
                an = ffma2(v.x, wn[2 * k2], an);
                ar = ffma2(v.y, wr[2 * k2 + 1], ar);
                az = ffma2(v.y, wz[2 * k2 + 1], az);
                an = ffma2(v.y, wn[2 * k2 + 1], an);
            }

            float lo, hi;
            upk2(ar, lo, hi); float r  = sigm_s(lo + hi);
            upk2(az, lo, hi); float z  = sigm_s(lo + hi);
            upk2(an, lo, hi); float hn = lo + hi;              // scaled hidden n-part + bn_h
            float n = tanh_s(fmaf(r, hn, sn));
            h = fmaf(z, h - n, n);            // (1-z)*n + z*h

            hbuf[warp][pp ^ 1][j] = h;
            pp ^= 1;
            __syncwarp();
        }

        // ============ backward GRU: exactly ONE step from h=0 (elementwise) ============
        {
            float xq = xp[TT - 1];
            const float wbr = Wihb[j], wbz = Wihb[j + 32], wbn = Wihb[j + 64];
            const float cbr  = bihb[j]      + bhhb[j];
            const float cbz  = bihb[j + 32] + bhhb[j + 32];
            const float cbni = bihb[j + 64];
            const float cbnh = bhhb[j + 64];
            float r = sigm(fmaf(xq, wbr, cbr));
            float z = sigm(fmaf(xq, wbz, cbz));
            float n = tanhfast(fmaf(r, cbnh, fmaf(xq, wbn, cbni)));
            float hbk = (1.0f - z) * n;
            vbuf[warp][j]      = h;
            vbuf[warp][HH + j] = hbk;
        }
    }
    __syncthreads();   // w1s/b1s/w2s staged + vbuf written (all warps arrive)

    // ================= MLP head: relu(v@W1.T+b1) @ W2.T + b2 -> sigmoid =========
    if (active && lane < 16) {
        const int u = lane;          // hidden unit
        const float b2v = __ldg(b2);
        const float* v = &vbuf[warp][0];
        float acc = b1s[u];
#pragma unroll
        for (int k = 0; k < 64; k++)
            acc = fmaf(w1s[u * 65 + k], v[k], acc);
        acc = fmaxf(acc, 0.0f);
        float tt = acc * w2s[u];
        tt += __shfl_xor_sync(0x0000ffffu, tt, 8, 16);
        tt += __shfl_xor_sync(0x0000ffffu, tt, 4, 16);
        tt += __shfl_xor_sync(0x0000ffffu, tt, 2, 16);
        tt += __shfl_xor_sync(0x0000ffffu, tt, 1, 16);
        if (u == 0) out[bb] = sigm(tt + b2v);
    }
}

extern "C" void kernel_launch(void* const* d_in, const int* in_sizes, int n_in,
                              void* d_out, int out_size) {
    const float* x    = (const float*)d_in[0];
    const float* Wihf = (const float*)d_in[1];
    const float* Whhf = (const float*)d_in[2];
    const float* bihf = (const float*)d_in[3];
    const float* bhhf = (const float*)d_in[4];
    const float* Wihb = (const float*)d_in[5];
    const float* Whhb = (const float*)d_in[6];
    const float* bihb = (const float*)d_in[7];
    const float* bhhb = (const float*)d_in[8];
    const float* W1   = (const float*)d_in[9];
    const float* b1   = (const float*)d_in[10];
    const float* W2   = (const float*)d_in[11];
    const float* b2   = (const float*)d_in[12];
    float* out = (float*)d_out;

    gru_bidir_kernel<<<NBLK, WPB * 32>>>(x, Wihf, Whhf, bihf, bhhf,
                                         Wihb, Whhb, bihb, bhhb,
                                         W1, b1, W2, b2, out);
}

// round 7
// speedup vs baseline: 1.1575x; 1.1575x over previous
#include <cuda_runtime.h>

#define NBLK 128
#define WPB  16       // warps per block -> 4 warps per SMSP
#define TT   512
#define HH   32

typedef unsigned long long u64;

__device__ __forceinline__ u64 pk2(float a, float b) {
    u64 r; asm("mov.b64 %0,{%1,%2};" : "=l"(r) : "f"(a), "f"(b)); return r;
}
__device__ __forceinline__ void upk2(u64 v, float& a, float& b) {
    asm("mov.b64 {%0,%1},%2;" : "=f"(a), "=f"(b) : "l"(v));
}
__device__ __forceinline__ u64 ffma2(u64 a, u64 b, u64 c) {
    u64 d; asm("fma.rn.f32x2 %0,%1,%2,%3;" : "=l"(d) : "l"(a), "l"(b), "l"(c)); return d;
}
__device__ __forceinline__ u64 fmul2(u64 a, u64 b) {
    u64 d; asm("mul.rn.f32x2 %0,%1,%2;" : "=l"(d) : "l"(a), "l"(b)); return d;
}
__device__ __forceinline__ float ex2f(float x) {
    float y; asm("ex2.approx.f32 %0,%1;" : "=f"(y) : "f"(x)); return y;
}
__device__ __forceinline__ float rcpf(float x) {
    float y; asm("rcp.approx.f32 %0,%1;" : "=f"(y) : "f"(x)); return y;
}
__device__ __forceinline__ float tanh_mufu(float x) {
    float y; asm("tanh.approx.f32 %0,%1;" : "=f"(y) : "f"(x)); return y;
}
// volatile LDS.64 (forces a reload, prevents keeping 16 u64 of h live)
__device__ __forceinline__ u64 lds_u64(const float* p) {
    u64 v;
    unsigned sa = (unsigned)__cvta_generic_to_shared((const void*)p);
    asm volatile("ld.shared.b64 %0, [%1];" : "=l"(v) : "r"(sa));
    return v;
}
// accurate versions for the one-off backward step + output
__device__ __forceinline__ float sigm(float v) {
    return rcpf(1.0f + ex2f(v * -1.4426950408889634f));
}
__device__ __forceinline__ float tanhfast(float v) {
    float s = rcpf(1.0f + ex2f(v * -2.8853900817779268f));
    return fmaf(2.0f, s, -1.0f);
}
// pre-scaled accurate tanh: arg already multiplied by -2log2e
__device__ __forceinline__ float tanh_s(float vs) {
    return fmaf(2.0f, rcpf(1.0f + ex2f(vs)), -1.0f);
}

#define N2L2E (-2.8853900817779268f)   // -2*log2(e)

__global__ void __launch_bounds__(WPB * 32, 1)
gru_bidir_kernel(const float* __restrict__ x,
                 const float* __restrict__ Wihf, const float* __restrict__ Whhf,
                 const float* __restrict__ bihf, const float* __restrict__ bhhf,
                 const float* __restrict__ Wihb, const float* __restrict__ Whhb,
                 const float* __restrict__ bihb, const float* __restrict__ bhhb,
                 const float* __restrict__ W1,  const float* __restrict__ b1,
                 const float* __restrict__ W2,  const float* __restrict__ b2,
                 float* __restrict__ out)
{
    __shared__ float xs[WPB][TT];                          // 32 KB: x staged, 1 batch/warp
    __shared__ __align__(16) float hbuf[WPB][2][HH];       // ping-pong hidden (read as u64)
    __shared__ __align__(16) float vbuf[WPB][2 * HH];      // concat(h_f, h_b) for MLP
    __shared__ float  w1s[16 * 65];                        // padded stride 65 -> conflict-free
    __shared__ float  b1s[16], w2s[16];

    const int tid  = threadIdx.x;
    const int lane = tid & 31;
    const int warp = tid >> 5;
    const int bb   = blockIdx.x * WPB + warp;  // batch row owned by this warp
    const int j    = lane;                     // hidden dim owned by this lane

    // ---- stage MLP weights (block-wide) ----
    for (int i = tid; i < 16 * 64; i += WPB * 32) {
        int u = i >> 6, k = i & 63;
        w1s[u * 65 + k] = W1[i];
    }
    if (tid < 16) { b1s[tid] = b1[tid]; w2s[tid] = W2[tid]; }

    // ---- stage this warp's x row ----
    for (int i = lane; i < TT; i += 32)
        xs[warp][i] = x[bb * TT + i];

    // ---- load recurrent weights, PRE-SCALED:
    //      r,z rows * 0.5 (sigma(v) = 0.5 + 0.5*tanh(v/2), MUFU.TANH path)
    //      n rows * -2log2e (accurate ex2/rcp tanh path) ----
    u64 wr[16], wz[16], wn[16];
    {
        const float2* pr = (const float2*)(Whhf + (j)      * HH);
        const float2* pz = (const float2*)(Whhf + (j + 32) * HH);
        const float2* pn = (const float2*)(Whhf + (j + 64) * HH);
#pragma unroll
        for (int k = 0; k < 16; k++) {
            float2 t0 = pr[k]; wr[k] = pk2(t0.x * 0.5f,  t0.y * 0.5f);
            float2 t1 = pz[k]; wz[k] = pk2(t1.x * 0.5f,  t1.y * 0.5f);
            float2 t2 = pn[k]; wn[k] = pk2(t2.x * N2L2E, t2.y * N2L2E);
        }
    }
    const float wxr = Wihf[j] * 0.5f, wxz = Wihf[j + 32] * 0.5f, wxn = Wihf[j + 64] * N2L2E;
    const float br   = (bihf[j]      + bhhf[j])      * 0.5f;
    const float bz   = (bihf[j + 32] + bhhf[j + 32]) * 0.5f;
    const float bn_i = bihf[j + 64] * N2L2E;     // input-side n bias (outside r*), scaled
    const float bn_h = bhhf[j + 64] * N2L2E;     // hidden-side n bias (inside r*), scaled

    // ---- init hidden state ----
    float h = 0.f;
    hbuf[warp][0][j] = 0.f;
    __syncwarp();

    const float* xp = &xs[warp][0];
    int pp = 0;

    // ================= forward GRU scan =================
#pragma unroll 1
    for (int t = 0; t < TT; t++) {
        float xv = xp[t];
        float sr = fmaf(xv, wxr, br);     // scaled 0.5
        float sz = fmaf(xv, wxz, bz);     // scaled 0.5
        float sn = fmaf(xv, wxn, bn_i);   // scaled -2log2e

        const float* hfp = &hbuf[warp][pp][0];
        const u64*   hb  = (const u64*)hfp;

        // ---- phase 1: r gate FIRST (2 sub-chains) so its MUFU chain
        //      retires while the z/n FFMA2 chains issue ----
        u64 ara = ffma2(hb[0], wr[0], pk2(sr, 0.f));
        u64 arb = fmul2(hb[1], wr[1]);
#pragma unroll
        for (int k = 2; k < 16; k += 2) {
            ara = ffma2(hb[k],     wr[k],     ara);
            arb = ffma2(hb[k + 1], wr[k + 1], arb);
        }
        float r;
        {
            float a0, a1, b0, b1;
            upk2(ara, a0, a1); upk2(arb, b0, b1);
            r = fmaf(0.5f, tanh_mufu((a0 + a1) + (b0 + b1)), 0.5f);
        }

        // ---- phase 2: z,n gates (h re-loaded via volatile LDS to cap regs) ----
        u64 hz = lds_u64(hfp);
        u64 az = ffma2(hz, wz[0], pk2(sz, 0.f));
        u64 an = ffma2(hz, wn[0], pk2(bn_h, 0.f));
#pragma unroll
        for (int k = 1; k < 16; k++) {
            hz = lds_u64(hfp + 2 * k);
            az = ffma2(hz, wz[k], az);
            an = ffma2(hz, wn[k], an);
        }
        float lo, hi;
        upk2(az, lo, hi);
        float z = fmaf(0.5f, tanh_mufu(lo + hi), 0.5f);
        upk2(an, lo, hi);
        float hn = lo + hi;                       // scaled hidden n-part (+bn_h folded)
        float n  = tanh_s(fmaf(r, hn, sn));       // accurate path for n
        h = fmaf(z, h - n, n);                    // (1-z)*n + z*h

        hbuf[warp][pp ^ 1][j] = h;
        pp ^= 1;
        __syncwarp();
    }

    // ============ backward GRU: exactly ONE step from h=0 (elementwise) ============
    {
        float xq = xp[TT - 1];
        const float wbr = Wihb[j], wbz = Wihb[j + 32], wbn = Wihb[j + 64];
        const float cbr  = bihb[j]      + bhhb[j];
        const float cbz  = bihb[j + 32] + bhhb[j + 32];
        const float cbni = bihb[j + 64];
        const float cbnh = bhhb[j + 64];
        float r = sigm(fmaf(xq, wbr, cbr));
        float z = sigm(fmaf(xq, wbz, cbz));
        float n = tanhfast(fmaf(r, cbnh, fmaf(xq, wbn, cbni)));
        float hbk = (1.0f - z) * n;
        vbuf[warp][j]      = h;
        vbuf[warp][HH + j] = hbk;
    }
    __syncthreads();   // w1s/b1s/w2s staged + vbuf written

    // ================= MLP head: relu(v@W1.T+b1) @ W2.T + b2 -> sigmoid =========
    if (lane < 16) {
        const int u = lane;          // hidden unit
        const float b2v = __ldg(b2);
        const float* v = &vbuf[warp][0];
        float acc = b1s[u];
#pragma unroll
        for (int k = 0; k < 64; k++)
            acc = fmaf(w1s[u * 65 + k], v[k], acc);
        acc = fmaxf(acc, 0.0f);
        float tt = acc * w2s[u];
        tt += __shfl_xor_sync(0x0000ffffu, tt, 8, 16);
        tt += __shfl_xor_sync(0x0000ffffu, tt, 4, 16);
        tt += __shfl_xor_sync(0x0000ffffu, tt, 2, 16);
        tt += __shfl_xor_sync(0x0000ffffu, tt, 1, 16);
        if (u == 0) out[bb] = sigm(tt + b2v);
    }
}

extern "C" void kernel_launch(void* const* d_in, const int* in_sizes, int n_in,
                              void* d_out, int out_size) {
    const float* x    = (const float*)d_in[0];
    const float* Wihf = (const float*)d_in[1];
    const float* Whhf = (const float*)d_in[2];
    const float* bihf = (const float*)d_in[3];
    const float* bhhf = (const float*)d_in[4];
    const float* Wihb = (const float*)d_in[5];
    const float* Whhb = (const float*)d_in[6];
    const float* bihb = (const float*)d_in[7];
    const float* bhhb = (const float*)d_in[8];
    const float* W1   = (const float*)d_in[9];
    const float* b1   = (const float*)d_in[10];
    const float* W2   = (const float*)d_in[11];
    const float* b2   = (const float*)d_in[12];
    float* out = (float*)d_out;

    gru_bidir_kernel<<<NBLK, WPB * 32>>>(x, Wihf, Whhf, bihf, bhhf,
                                         Wihb, Whhb, bihb, bhhb,
                                         W1, b1, W2, b2, out);
}

// round 9
// speedup vs baseline: 1.2869x; 1.1118x over previous
#include <cuda_runtime.h>

#define NBLK 128
#define WPB  16       // warps per block -> 4 warps per SMSP
#define TT   512
#define HH   32

typedef unsigned long long u64;

__device__ __forceinline__ u64 pk2(float a, float b) {
    u64 r; asm("mov.b64 %0,{%1,%2};" : "=l"(r) : "f"(a), "f"(b)); return r;
}
__device__ __forceinline__ void upk2(u64 v, float& a, float& b) {
    asm("mov.b64 {%0,%1},%2;" : "=f"(a), "=f"(b) : "l"(v));
}
__device__ __forceinline__ u64 ffma2(u64 a, u64 b, u64 c) {
    u64 d; asm("fma.rn.f32x2 %0,%1,%2,%3;" : "=l"(d) : "l"(a), "l"(b), "l"(c)); return d;
}
__device__ __forceinline__ u64 fmul2(u64 a, u64 b) {
    u64 d; asm("mul.rn.f32x2 %0,%1,%2;" : "=l"(d) : "l"(a), "l"(b)); return d;
}
__device__ __forceinline__ u64 fadd2(u64 a, u64 b) {
    u64 d; asm("add.rn.f32x2 %0,%1,%2;" : "=l"(d) : "l"(a), "l"(b)); return d;
}
__device__ __forceinline__ float ex2f(float x) {
    float y; asm("ex2.approx.f32 %0,%1;" : "=f"(y) : "f"(x)); return y;
}
__device__ __forceinline__ float rcpf(float x) {
    float y; asm("rcp.approx.f32 %0,%1;" : "=f"(y) : "f"(x)); return y;
}
__device__ __forceinline__ float tanh_mufu(float x) {
    float y; asm("tanh.approx.f32 %0,%1;" : "=f"(y) : "f"(x)); return y;
}
// volatile LDS.128: two u64 halves of h, forces reload (caps register pressure)
__device__ __forceinline__ void lds_u64x2(const float* p, u64& a, u64& b) {
    unsigned sa = (unsigned)__cvta_generic_to_shared((const void*)p);
    asm volatile("ld.shared.v2.b64 {%0,%1}, [%2];" : "=l"(a), "=l"(b) : "r"(sa));
}
// accurate versions for the one-off backward step + output
__device__ __forceinline__ float sigm(float v) {
    return rcpf(1.0f + ex2f(v * -1.4426950408889634f));
}
__device__ __forceinline__ float tanhfast(float v) {
    float s = rcpf(1.0f + ex2f(v * -2.8853900817779268f));
    return fmaf(2.0f, s, -1.0f);
}

__global__ void __launch_bounds__(WPB * 32, 1)
gru_bidir_kernel(const float* __restrict__ x,
                 const float* __restrict__ Wihf, const float* __restrict__ Whhf,
                 const float* __restrict__ bihf, const float* __restrict__ bhhf,
                 const float* __restrict__ Wihb, const float* __restrict__ Whhb,
                 const float* __restrict__ bihb, const float* __restrict__ bhhb,
                 const float* __restrict__ W1,  const float* __restrict__ b1,
                 const float* __restrict__ W2,  const float* __restrict__ b2,
                 float* __restrict__ out)
{
    __shared__ float xs[WPB][TT];                          // 32 KB: x staged, 1 batch/warp
    __shared__ __align__(16) float hbuf[WPB][2][HH];       // ping-pong hidden (read as u64x2)
    __shared__ __align__(16) float vbuf[WPB][2 * HH];      // concat(h_f, h_b) for MLP
    __shared__ float  w1s[16 * 65];                        // padded stride 65 -> conflict-free
    __shared__ float  b1s[16], w2s[16];

    const int tid  = threadIdx.x;
    const int lane = tid & 31;
    const int warp = tid >> 5;
    const int bb   = blockIdx.x * WPB + warp;  // batch row owned by this warp
    const int j    = lane;                     // hidden dim owned by this lane

    // ---- stage MLP weights (block-wide) ----
    for (int i = tid; i < 16 * 64; i += WPB * 32) {
        int u = i >> 6, k = i & 63;
        w1s[u * 65 + k] = W1[i];
    }
    if (tid < 16) { b1s[tid] = b1[tid]; w2s[tid] = W2[tid]; }

    // ---- stage this warp's x row ----
    for (int i = lane; i < TT; i += 32)
        xs[warp][i] = x[bb * TT + i];

    // ---- load recurrent weights, K-packed into f32x2 pairs.
    //      r,z rows PRE-SCALED by 0.5: sigma(v) = 0.5 + 0.5*tanh(v/2) via MUFU.TANH.
    //      n rows raw: n = tanh(v) via MUFU.TANH. ----
    u64 wr[16], wz[16], wn[16];
    {
        const float2* pr = (const float2*)(Whhf + (j)      * HH);
        const float2* pz = (const float2*)(Whhf + (j + 32) * HH);
        const float2* pn = (const float2*)(Whhf + (j + 64) * HH);
#pragma unroll
        for (int k = 0; k < 16; k++) {
            float2 t0 = pr[k]; wr[k] = pk2(t0.x * 0.5f, t0.y * 0.5f);
            float2 t1 = pz[k]; wz[k] = pk2(t1.x * 0.5f, t1.y * 0.5f);
            float2 t2 = pn[k]; wn[k] = pk2(t2.x, t2.y);
        }
    }
    const float wxr = Wihf[j] * 0.5f, wxz = Wihf[j + 32] * 0.5f, wxn = Wihf[j + 64];
    const float br   = (bihf[j]      + bhhf[j])      * 0.5f;
    const float bz   = (bihf[j + 32] + bhhf[j + 32]) * 0.5f;
    const float bn_i = bihf[j + 64];     // input-side n bias (outside r*)
    const float bn_h = bhhf[j + 64];     // hidden-side n bias (inside r*)

    // ---- init hidden state ----
    float h = 0.f;
    hbuf[warp][0][j] = 0.f;
    __syncwarp();

    const float* xp = &xs[warp][0];
    float* const hb0 = &hbuf[warp][0][0];
    float* const hb1 = &hbuf[warp][1][0];

    // ================= forward GRU scan (unrolled x2 over ping-pong) =================
#pragma unroll 1
    for (int t = 0; t < TT; t += 2) {
#pragma unroll
        for (int half = 0; half < 2; half++) {
            const float* hfp = half ? hb1 : hb0;
            float*       hwp = half ? hb0 : hb1;
            float xv = xp[t + half];
            float sr = fmaf(xv, wxr, br);     // scaled 0.5
            float sz = fmaf(xv, wxz, bz);     // scaled 0.5
            float sn = fmaf(xv, wxn, bn_i);   // raw

            // ---- phase 1: r gate FIRST (2 sub-chains) so its MUFU chain
            //      retires while the z/n FFMA2 chains issue ----
            u64 p0, p1;
            lds_u64x2(hfp + 0, p0, p1);
            u64 ara = ffma2(p0, wr[0], pk2(sr, 0.f));
            u64 arb = fmul2(p1, wr[1]);
#pragma unroll
            for (int k = 1; k < 8; k++) {
                lds_u64x2(hfp + 4 * k, p0, p1);
                ara = ffma2(p0, wr[2 * k],     ara);
                arb = ffma2(p1, wr[2 * k + 1], arb);
            }
            float r;
            {
                u64 s = fadd2(ara, arb);
                float lo, hi; upk2(s, lo, hi);
                r = fmaf(0.5f, tanh_mufu(lo + hi), 0.5f);
            }

            // ---- phase 2: z,n gates (h re-loaded volatile to cap regs) ----
            lds_u64x2(hfp + 0, p0, p1);
            u64 az = ffma2(p0, wz[0], pk2(sz, 0.f));
            u64 an = ffma2(p0, wn[0], pk2(bn_h, 0.f));
            az = ffma2(p1, wz[1], az);
            an = ffma2(p1, wn[1], an);
#pragma unroll
            for (int k = 1; k < 8; k++) {
                lds_u64x2(hfp + 4 * k, p0, p1);
                az = ffma2(p0, wz[2 * k], az);
                an = ffma2(p0, wn[2 * k], an);
                az = ffma2(p1, wz[2 * k + 1], az);
                an = ffma2(p1, wn[2 * k + 1], an);
            }
            float lo, hi;
            upk2(az, lo, hi);
            float z = fmaf(0.5f, tanh_mufu(lo + hi), 0.5f);
            upk2(an, lo, hi);
            float hn = lo + hi;                       // raw hidden n-part (+bn_h folded)
            float n  = tanh_mufu(fmaf(r, hn, sn));    // MUFU tanh for n
            h = fmaf(z, h - n, n);                    // (1-z)*n + z*h

            hwp[j] = h;
            __syncwarp();
        }
    }

    // ============ backward GRU: exactly ONE step from h=0 (elementwise) ============
    {
        float xq = xp[TT - 1];
        const float wbr = Wihb[j], wbz = Wihb[j + 32], wbn = Wihb[j + 64];
        const float cbr  = bihb[j]      + bhhb[j];
        const float cbz  = bihb[j + 32] + bhhb[j + 32];
        const float cbni = bihb[j + 64];
        const float cbnh = bhhb[j + 64];
        float r = sigm(fmaf(xq, wbr, cbr));
        float z = sigm(fmaf(xq, wbz, cbz));
        float n = tanhfast(fmaf(r, cbnh, fmaf(xq, wbn, cbni)));
        float hbk = (1.0f - z) * n;
        vbuf[warp][j]      = h;
        vbuf[warp][HH + j] = hbk;
    }
    __syncthreads();   // w1s/b1s/w2s staged + vbuf written

    // ================= MLP head: relu(v@W1.T+b1) @ W2.T + b2 -> sigmoid =========
    if (lane < 16) {
        const int u = lane;          // hidden unit
        const float b2v = __ldg(b2);
        const float* v = &vbuf[warp][0];
        float acc = b1s[u];
#pragma unroll
        for (int k = 0; k < 64; k++)
            acc = fmaf(w1s[u * 65 + k], v[k], acc);
        acc = fmaxf(acc, 0.0f);
        float tt = acc * w2s[u];
        tt += __shfl_xor_sync(0x0000ffffu, tt, 8, 16);
        tt += __shfl_xor_sync(0x0000ffffu, tt, 4, 16);
        tt += __shfl_xor_sync(0x0000ffffu, tt, 2, 16);
        tt += __shfl_xor_sync(0x0000ffffu, tt, 1, 16);
        if (u == 0) out[bb] = sigm(tt + b2v);
    }
}

extern "C" void kernel_launch(void* const* d_in, const int* in_sizes, int n_in,
                              void* d_out, int out_size) {
    const float* x    = (const float*)d_in[0];
    const float* Wihf = (const float*)d_in[1];
    const float* Whhf = (const float*)d_in[2];
    const float* bihf = (const float*)d_in[3];
    const float* bhhf = (const float*)d_in[4];
    const float* Wihb = (const float*)d_in[5];
    const float* Whhb = (const float*)d_in[6];
    const float* bihb = (const float*)d_in[7];
    const float* bhhb = (const float*)d_in[8];
    const float* W1   = (const float*)d_in[9];
    const float* b1   = (const float*)d_in[10];
    const float* W2   = (const float*)d_in[11];
    const float* b2   = (const float*)d_in[12];
    float* out = (float*)d_out;

    gru_bidir_kernel<<<NBLK, WPB * 32>>>(x, Wihf, Whhf, bihf, bhhf,
                                         Wihb, Whhb, bihb, bhhb,
                                         W1, b1, W2, b2, out);
}